// round 5
// baseline (speedup 1.0000x reference)
#include <cuda_runtime.h>
#include <math.h>

#define NN   50000
#define EE   800000
#define CC   5000
#define DD   128
#define OUTF 40
#define CAP  64          // per-node in-edge bin capacity (max deg ~38)
#define RS   64          // padded feature row stride (floats) -> 256B aligned
#define RS4  16          // row stride in float4

// ---- scratch (device globals; no allocation allowed) ----
__device__ int   g_cnt[NN];            // in-degree counts (also bin cursors)
__device__ int   g_srcbuf[NN * CAP];   // binned in-edge source lists
__device__ float g_dinv[NN];           // D^{-1/2}
__device__ float g_xps[NN * RS];       // dinv[v] * (x[v] @ W^T), padded rows
__device__ float g_h1s[NN * RS];       // dinv[v] * h1[v], padded rows
__device__ float g_ycn[CC * OUTF];     // per-cluster log-softmax'd logits

// ---- f32x2 packed helpers (Blackwell FFMA2) ----
__device__ __forceinline__ unsigned long long pk2(float lo, float hi) {
    unsigned long long r;
    asm("mov.b64 %0, {%1, %2};" : "=l"(r) : "f"(lo), "f"(hi));
    return r;
}
__device__ __forceinline__ unsigned long long fma2(unsigned long long a,
                                                   unsigned long long b,
                                                   unsigned long long c) {
    unsigned long long d;
    asm("fma.rn.f32x2 %0, %1, %2, %3;" : "=l"(d) : "l"(a), "l"(b), "l"(c));
    return d;
}
__device__ __forceinline__ void upk2(unsigned long long v, float& a, float& b) {
    asm("mov.b64 {%0, %1}, %2;" : "=f"(a), "=f"(b) : "l"(v));
}

__device__ __forceinline__ void acc4(float4& a, const float4& t) {
    a.x += t.x; a.y += t.y; a.z += t.z; a.w += t.w;
}

// ---------------------------------------------------------------------------
// One pass: count in-degree AND place edge sources into per-dst bins.
// 4 edges per thread via int4 loads of src/dst rows.
__global__ void fill_kernel(const int* __restrict__ ei) {
    int e4 = blockIdx.x * blockDim.x + threadIdx.x;
    if (e4 >= EE / 4) return;
    int4 s = __ldg(((const int4*)ei) + e4);
    int4 d = __ldg(((const int4*)(ei + EE)) + e4);
    int p0 = atomicAdd(&g_cnt[d.x], 1);
    if (p0 < CAP) g_srcbuf[d.x * CAP + p0] = s.x;
    int p1 = atomicAdd(&g_cnt[d.y], 1);
    if (p1 < CAP) g_srcbuf[d.y * CAP + p1] = s.y;
    int p2 = atomicAdd(&g_cnt[d.z], 1);
    if (p2 < CAP) g_srcbuf[d.z * CAP + p2] = s.z;
    int p3 = atomicAdd(&g_cnt[d.w], 1);
    if (p3 < CAP) g_srcbuf[d.w * CAP + p3] = s.w;
}

// ---------------------------------------------------------------------------
// xps[v] = dinv[v] * (x[v] @ W^T); also computes/stores dinv from counts.
// W pre-paired in shared as f32x2 pairs over output dim; FFMA2 inner loop.
__global__ void proj_kernel(const float* __restrict__ x,
                            const float* __restrict__ W) {
    __shared__ ulonglong2 Ws2[OUTF / 2][DD / 2];   // 20KB
    for (int t = threadIdx.x; t < (OUTF / 2) * (DD / 2); t += blockDim.x) {
        int o2 = t / (DD / 2);
        int d2 = t % (DD / 2);
        int d  = 2 * d2;
        float w00 = W[(2 * o2)     * DD + d    ];
        float w10 = W[(2 * o2 + 1) * DD + d    ];
        float w01 = W[(2 * o2)     * DD + d + 1];
        float w11 = W[(2 * o2 + 1) * DD + d + 1];
        Ws2[o2][d2] = make_ulonglong2(pk2(w00, w10), pk2(w01, w11));
    }
    __syncthreads();

    int row = blockIdx.x * blockDim.x + threadIdx.x;
    if (row >= NN) return;

    unsigned long long acc[OUTF / 2];
    #pragma unroll
    for (int o2 = 0; o2 < OUTF / 2; o2++) acc[o2] = 0ull;

    const float4* xr4 = (const float4*)(x + (size_t)row * DD);
    #pragma unroll 4
    for (int d4 = 0; d4 < DD / 4; d4++) {
        float4 xv = __ldg(&xr4[d4]);
        int d2 = d4 * 2;
        unsigned long long a0 = pk2(xv.x, xv.x);
        unsigned long long a1 = pk2(xv.y, xv.y);
        unsigned long long a2 = pk2(xv.z, xv.z);
        unsigned long long a3 = pk2(xv.w, xv.w);
        #pragma unroll
        for (int o2 = 0; o2 < OUTF / 2; o2++) {
            ulonglong2 w = Ws2[o2][d2];
            acc[o2] = fma2(a0, w.x, acc[o2]);
            acc[o2] = fma2(a1, w.y, acc[o2]);
        }
        #pragma unroll
        for (int o2 = 0; o2 < OUTF / 2; o2++) {
            ulonglong2 w = Ws2[o2][d2 + 1];
            acc[o2] = fma2(a2, w.x, acc[o2]);
            acc[o2] = fma2(a3, w.y, acc[o2]);
        }
    }

    float dv = rsqrtf((float)(g_cnt[row] + 1));   // +1 self loop
    g_dinv[row] = dv;
    float2* op2 = (float2*)(g_xps + (size_t)row * RS);
    #pragma unroll
    for (int o2 = 0; o2 < OUTF / 2; o2++) {
        float f0, f1;
        upk2(acc[o2], f0, f1);
        op2[o2] = make_float2(dv * f0, dv * f1);
    }
}

// ---------------------------------------------------------------------------
// Shared gather-sum core: acc = row[v] + sum_in rows[s], 8-wide edge unroll.
// One warp per node; lanes 0..9 each own a float4 chunk (40 floats).
__device__ __forceinline__ float4 gather_row_sum(const float4* __restrict__ rows4,
                                                 int v, int lane, bool act) {
    float4 acc = make_float4(0.f, 0.f, 0.f, 0.f);
    if (act) acc = __ldg(&rows4[(size_t)v * RS4 + lane]);
    int deg = g_cnt[v];
    if (deg > CAP) deg = CAP;
    const int* sb = g_srcbuf + v * CAP;
    int i = 0;
    for (; i + 8 <= deg; i += 8) {
        int4 sa = __ldg((const int4*)(sb + i));
        int4 sc = __ldg((const int4*)(sb + i + 4));
        if (act) {
            float4 t0 = __ldg(&rows4[(size_t)sa.x * RS4 + lane]);
            float4 t1 = __ldg(&rows4[(size_t)sa.y * RS4 + lane]);
            float4 t2 = __ldg(&rows4[(size_t)sa.z * RS4 + lane]);
            float4 t3 = __ldg(&rows4[(size_t)sa.w * RS4 + lane]);
            float4 t4 = __ldg(&rows4[(size_t)sc.x * RS4 + lane]);
            float4 t5 = __ldg(&rows4[(size_t)sc.y * RS4 + lane]);
            float4 t6 = __ldg(&rows4[(size_t)sc.z * RS4 + lane]);
            float4 t7 = __ldg(&rows4[(size_t)sc.w * RS4 + lane]);
            acc4(acc, t0); acc4(acc, t1); acc4(acc, t2); acc4(acc, t3);
            acc4(acc, t4); acc4(acc, t5); acc4(acc, t6); acc4(acc, t7);
        }
    }
    if (i + 4 <= deg) {
        int4 sa = __ldg((const int4*)(sb + i));
        if (act) {
            float4 t0 = __ldg(&rows4[(size_t)sa.x * RS4 + lane]);
            float4 t1 = __ldg(&rows4[(size_t)sa.y * RS4 + lane]);
            float4 t2 = __ldg(&rows4[(size_t)sa.z * RS4 + lane]);
            float4 t3 = __ldg(&rows4[(size_t)sa.w * RS4 + lane]);
            acc4(acc, t0); acc4(acc, t1); acc4(acc, t2); acc4(acc, t3);
        }
        i += 4;
    }
    for (; i < deg; i++) {
        int s = __ldg(&sb[i]);
        if (act) {
            float4 t = __ldg(&rows4[(size_t)s * RS4 + lane]);
            acc4(acc, t);
        }
    }
    return acc;
}

// hop 1 (all nodes): h1s[v] = dinv[v]^2 * ( xps[v] + sum_in xps[s] )
__global__ void hop1_kernel() {
    int warp = (blockIdx.x * blockDim.x + threadIdx.x) >> 5;
    int lane = threadIdx.x & 31;
    if (warp >= NN) return;
    int v = warp;
    const bool act = (lane < 10);
    float4 acc = gather_row_sum((const float4*)g_xps, v, lane, act);
    float dv = g_dinv[v];
    float sc = dv * dv;
    if (act) {
        ((float4*)g_h1s)[(size_t)v * RS4 + lane] =
            make_float4(sc * acc.x, sc * acc.y, sc * acc.z, sc * acc.w);
    }
}

// hop 2 (rep rows only) + bias + fused log_softmax -> g_ycn
__global__ void hop2_kernel(const int* __restrict__ rep_idx,
                            const float* __restrict__ b) {
    int warp = (blockIdx.x * blockDim.x + threadIdx.x) >> 5;
    int lane = threadIdx.x & 31;
    if (warp >= CC) return;
    int j = warp;
    int v = __ldg(&rep_idx[j]);
    const bool act = (lane < 10);
    float4 acc = gather_row_sum((const float4*)g_h1s, v, lane, act);

    float dv = g_dinv[v];
    float4 bb = make_float4(0.f, 0.f, 0.f, 0.f);
    if (act) bb = __ldg(&((const float4*)b)[lane]);
    float4 val;
    val.x = dv * acc.x + bb.x;
    val.y = dv * acc.y + bb.y;
    val.z = dv * acc.z + bb.z;
    val.w = dv * acc.w + bb.w;

    // warp-level log_softmax over the 40 values held by lanes 0..9
    float m = act ? fmaxf(fmaxf(val.x, val.y), fmaxf(val.z, val.w)) : -INFINITY;
    #pragma unroll
    for (int off = 16; off > 0; off >>= 1)
        m = fmaxf(m, __shfl_xor_sync(0xFFFFFFFFu, m, off));
    float e = act ? (expf(val.x - m) + expf(val.y - m) +
                     expf(val.z - m) + expf(val.w - m)) : 0.0f;
    #pragma unroll
    for (int off = 16; off > 0; off >>= 1)
        e += __shfl_xor_sync(0xFFFFFFFFu, e, off);
    float lse = m + logf(e);

    if (act) {
        ((float4*)g_ycn)[(size_t)j * (OUTF / 4) + lane] =
            make_float4(val.x - lse, val.y - lse, val.z - lse, val.w - lse);
    }
}

// ---------------------------------------------------------------------------
// out[i] = ycn[cluster_index[i]]   (pure float4 gather-copy)
__global__ void gather_out_kernel(const int* __restrict__ cluster_index,
                                  float4* __restrict__ out4) {
    int t = blockIdx.x * blockDim.x + threadIdx.x;
    const int TOT = NN * (OUTF / 4);               // 500000 float4s
    if (t >= TOT) return;
    int node = t / (OUTF / 4);
    int j    = t - node * (OUTF / 4);
    int cl = __ldg(&cluster_index[node]);
    out4[t] = __ldg(((const float4*)g_ycn) + (size_t)cl * (OUTF / 4) + j);
}

// ---------------------------------------------------------------------------
extern "C" void kernel_launch(void* const* d_in, const int* in_sizes, int n_in,
                              void* d_out, int out_size) {
    const float* x             = (const float*)d_in[0];
    const int*   edge_index    = (const int*)d_in[1];
    const int*   cluster_index = (const int*)d_in[2];
    const int*   rep_idx       = (const int*)d_in[3];
    const float* W             = (const float*)d_in[4];
    const float* b             = (const float*)d_in[5];
    float4*      out4          = (float4*)d_out;

    // zero the degree counters (memset node in the graph)
    void* cntp = nullptr;
    cudaGetSymbolAddress(&cntp, g_cnt);
    cudaMemsetAsync(cntp, 0, NN * sizeof(int), 0);

    // build binned in-edge lists (count + place in one pass, 4 edges/thread)
    fill_kernel<<<(EE / 4 + 255) / 256, 256>>>(edge_index);

    // project then propagate (SGC: A^2 (x W^T) == (A^2 x) W^T), scales folded in
    proj_kernel<<<(NN + 255) / 256, 256>>>(x, W);
    hop1_kernel<<<(NN * 32 + 255) / 256, 256>>>();
    hop2_kernel<<<(CC * 32 + 255) / 256, 256>>>(rep_idx, b);

    // scatter normalized logits
    gather_out_kernel<<<(NN * (OUTF / 4) + 255) / 256, 256>>>(cluster_index, out4);
}